// round 8
// baseline (speedup 1.0000x reference)
#include <cuda_runtime.h>
#include <cuda_bf16.h>
#include <cuda_fp16.h>
#include <cstdint>

// Problem constants (fixed by the dataset)
#define NN   50000
#define NPAD 50176        // 196 * 256
#define EE   800000
#define FIN  3
#define HH   256
#define GG   64
#define OUTD 24

// ---------------- scratch (device globals; no allocation allowed) -----------
__device__ float g_hf[NN * HH];           // final-layer fp32 activations (for pooling)
__device__ __half g_yh[(size_t)NN * HH];  // h @ w_rel, fp16 (gather payload)
__device__ __half g_zh[(size_t)NN * HH];  // h @ w_root + b, fp16
__device__ float g_agg3[NN * FIN];
__device__ float g_pooled[GG * HH];
__device__ int   g_deg[NN + 1];
__device__ int   g_rowptr[NN + 1];
__device__ int   g_cursor[NN + 1];
__device__ int   g_csr[EE];
__device__ int   g_bsums[256];
// tensor-core path scratch
__device__ __nv_bfloat16 g_A2[(size_t)NPAD * 512];      // [row][0..255]=hi, [256..511]=lo (pad rows: zero)
__device__ __nv_bfloat16 g_Bp[(size_t)6 * 512 * 768];   // per layer: [n(512)][k'(768)] = [hi|hi|lo]

// ---------------- PTX helpers (family-safe only: mma.sync / ldmatrix / cp.async)
__device__ __forceinline__ uint32_t smem_u32(const void* p) {
    uint32_t a;
    asm("{ .reg .u64 t; cvta.to.shared.u64 t, %1; cvt.u32.u64 %0, t; }" : "=r"(a) : "l"(p));
    return a;
}
__device__ __forceinline__ void cp16(uint32_t saddr, const void* gptr) {
    asm volatile("cp.async.cg.shared.global [%0], [%1], 16;" :: "r"(saddr), "l"(gptr) : "memory");
}
__device__ __forceinline__ void cp_commit() {
    asm volatile("cp.async.commit_group;" ::: "memory");
}
__device__ __forceinline__ void cp_wait1() {
    asm volatile("cp.async.wait_group 1;" ::: "memory");
}
__device__ __forceinline__ void cp_wait0() {
    asm volatile("cp.async.wait_group 0;" ::: "memory");
}
__device__ __forceinline__ void ldmx4(uint32_t* r, uint32_t addr) {
    asm volatile("ldmatrix.sync.aligned.m8n8.x4.shared.b16 {%0,%1,%2,%3}, [%4];"
                 : "=r"(r[0]), "=r"(r[1]), "=r"(r[2]), "=r"(r[3]) : "r"(addr));
}
__device__ __forceinline__ void mma16816(float* c, const uint32_t* a, uint32_t b0, uint32_t b1) {
    asm volatile(
        "mma.sync.aligned.m16n8k16.row.col.f32.bf16.bf16.f32 "
        "{%0,%1,%2,%3}, {%4,%5,%6,%7}, {%8,%9}, {%0,%1,%2,%3};"
        : "+f"(c[0]), "+f"(c[1]), "+f"(c[2]), "+f"(c[3])
        : "r"(a[0]), "r"(a[1]), "r"(a[2]), "r"(a[3]), "r"(b0), "r"(b1));
}
// 128B-atom XOR swizzle (bank-conflict-free STS/ldmatrix)
__device__ __forceinline__ uint32_t SWZ(uint32_t x) { return x ^ ((x >> 3) & 0x70); }

// ---------------- CSR construction ------------------------------------------
__global__ void zero_int_kernel(int* a, int n) {
    int i = blockIdx.x * blockDim.x + threadIdx.x;
    if (i < n) a[i] = 0;
}

__global__ void count_deg_kernel(const int* __restrict__ dst, int* __restrict__ deg, int e) {
    int i = blockIdx.x * blockDim.x + threadIdx.x;
    if (i < e) atomicAdd(&deg[dst[i]], 1);
}

// ---- parallel exclusive scan over NN elems: 3 phases, 256-elem blocks ----
#define SCAN_BLOCKS ((NN + 255) / 256)   // 196

__global__ void scan_pass1(const int* __restrict__ deg, int* __restrict__ bsums, int n) {
    int i = blockIdx.x * 256 + threadIdx.x;
    int v = (i < n) ? deg[i] : 0;
    #pragma unroll
    for (int o = 16; o > 0; o >>= 1) v += __shfl_down_sync(0xFFFFFFFF, v, o);
    __shared__ int ws[8];
    int wid = threadIdx.x >> 5, lane = threadIdx.x & 31;
    if (lane == 0) ws[wid] = v;
    __syncthreads();
    if (threadIdx.x == 0) {
        int s = 0;
        #pragma unroll
        for (int w = 0; w < 8; w++) s += ws[w];
        bsums[blockIdx.x] = s;
    }
}

__global__ void scan_pass2(int* __restrict__ bsums, int nb) {
    __shared__ int sh[256];
    int tid = threadIdx.x;
    int v = (tid < nb) ? bsums[tid] : 0;
    sh[tid] = v;
    __syncthreads();
    #pragma unroll
    for (int off = 1; off < 256; off <<= 1) {
        int t = (tid >= off) ? sh[tid - off] : 0;
        __syncthreads();
        sh[tid] += t;
        __syncthreads();
    }
    if (tid < nb) bsums[tid] = sh[tid] - v;   // exclusive
}

__global__ void scan_pass3(const int* __restrict__ deg, const int* __restrict__ bsums,
                           int* __restrict__ rowptr, int n) {
    __shared__ int sh[256];
    int i = blockIdx.x * 256 + threadIdx.x;
    int tid = threadIdx.x;
    int v = (i < n) ? deg[i] : 0;
    sh[tid] = v;
    __syncthreads();
    #pragma unroll
    for (int off = 1; off < 256; off <<= 1) {
        int t = (tid >= off) ? sh[tid - off] : 0;
        __syncthreads();
        sh[tid] += t;
        __syncthreads();
    }
    int incl = sh[tid];
    int base = bsums[blockIdx.x];
    if (i < n)  rowptr[i] = base + incl - v;
    if (i == n - 1) rowptr[n] = base + incl;
}

__global__ void fill_csr_kernel(const int* __restrict__ src, const int* __restrict__ dst,
                                const int* __restrict__ rowptr, int* __restrict__ cursor,
                                int* __restrict__ csr, int e) {
    int i = blockIdx.x * blockDim.x + threadIdx.x;
    if (i < e) {
        int d = dst[i];
        int pos = atomicAdd(&cursor[d], 1);
        csr[rowptr[d] + pos] = src[i];
    }
}

// ---------------- layer 1 (F_IN=3 -> H), writes A2 hi/lo directly ------------
__global__ void aggx_kernel(const float* __restrict__ x,
                            const int* __restrict__ rowptr, const int* __restrict__ csr,
                            float* __restrict__ agg3, int n) {
    int i = blockIdx.x * blockDim.x + threadIdx.x;
    if (i >= n) return;
    float a0 = 0.f, a1 = 0.f, a2 = 0.f;
    int beg = rowptr[i], end = rowptr[i + 1];
    for (int e = beg; e < end; e++) {
        int s = csr[e];
        a0 += x[s * 3 + 0];
        a1 += x[s * 3 + 1];
        a2 += x[s * 3 + 2];
    }
    agg3[i * 3 + 0] = a0;
    agg3[i * 3 + 1] = a1;
    agg3[i * 3 + 2] = a2;
}

__global__ void layer1_kernel(const float* __restrict__ x, const float* __restrict__ agg3,
                              const float* __restrict__ wr, const float* __restrict__ wro,
                              const float* __restrict__ b1, __nv_bfloat16* __restrict__ A2) {
    int n = blockIdx.x;
    int j = threadIdx.x;  // 256
    __shared__ float sx[3], sa[3];
    if (j < 3) { sx[j] = x[n * 3 + j]; sa[j] = agg3[n * 3 + j]; }
    __syncthreads();
    float v = b1[j];
    #pragma unroll
    for (int f = 0; f < 3; f++)
        v += sa[f] * wr[f * HH + j] + sx[f] * wro[f * HH + j];
    v = fmaxf(v, 0.f);
    __nv_bfloat16 hi = __float2bfloat16(v);
    __nv_bfloat16 lo = __float2bfloat16(v - __bfloat162float(hi));
    A2[(size_t)n * 512 + j]       = hi;
    A2[(size_t)n * 512 + 256 + j] = lo;
}

// ---------------- weight prep: fp32 [K,N] -> bf16 hi/lo, [N][768] K-major ----
__global__ void prep_weights_kernel(const float* __restrict__ w_rel, const float* __restrict__ w_root,
                                    __nv_bfloat16* __restrict__ Bp) {
    int idx = blockIdx.x * blockDim.x + threadIdx.x;
    if (idx >= 6 * 512 * 256) return;
    int k = idx & 255;
    int n = (idx >> 8) & 511;
    int L = idx >> 17;
    float w = (n < 256) ? w_rel[(size_t)L * 65536 + k * 256 + n]
                        : w_root[(size_t)L * 65536 + k * 256 + (n - 256)];
    __nv_bfloat16 hi = __float2bfloat16(w);
    __nv_bfloat16 lo = __float2bfloat16(w - __bfloat162float(hi));
    __nv_bfloat16* bp = Bp + (size_t)L * 512 * 768 + (size_t)n * 768;
    bp[k]       = hi;
    bp[256 + k] = hi;
    bp[512 + k] = lo;
}

// ---------------- mma.sync GEMM ----------------------------------------------
// C[256,128] per CTA; C = A'[M,768] x B'^T, A' chunks (hi,lo,hi) vs B' (hi,hi,lo).
// grid (196, 4): blockIdx.y 0,1 -> Yh cols 0/128; 2,3 -> Zh cols 0/128 (+bias).
// 16 warps: wm = wid>>1 (8 x 32 rows), wn = wid&1 (2 x 64 cols).
// SMEM: 2 stages x (A 32KB + B 16KB) = 96KB, cp.async double-buffered.
#define GEMM_STAGE   49152
#define GEMM_SMEM_TOTAL (2 * GEMM_STAGE)

__device__ __forceinline__ void load_chunk_cp(uint32_t sdst, int c, int bm, int nb,
                                              const __nv_bfloat16* __restrict__ A2,
                                              const __nv_bfloat16* __restrict__ Bp) {
    int tid = threadIdx.x;  // 512
    int kmap = (c < 8) ? c * 64 : (c - 8) * 64;   // A chunks: 0-3 hi, 4-7 lo, 8-11 hi
    #pragma unroll
    for (int i = 0; i < 4; i++) {                  // A: 256 rows x 128B = 2048 x 16B
        int v = tid + i * 512;
        int r = v >> 3, kc = v & 7;
        const void* g = A2 + (size_t)(bm + r) * 512 + kmap + kc * 8;
        cp16(sdst + SWZ(r * 128 + kc * 16), g);
    }
    uint32_t bdst = sdst + 32768;
    #pragma unroll
    for (int i = 0; i < 2; i++) {                  // B: 128 n-rows x 128B = 1024 x 16B
        int v = tid + i * 512;
        int r = v >> 3, kc = v & 7;
        const void* g = Bp + (size_t)(nb * 128 + r) * 768 + c * 64 + kc * 8;
        cp16(bdst + SWZ(r * 128 + kc * 16), g);
    }
}

__global__ __launch_bounds__(512)
void gemm_tc_kernel(const __nv_bfloat16* __restrict__ A2, const __nv_bfloat16* __restrict__ Bp,
                    const float* __restrict__ bias, __half* __restrict__ Yh, __half* __restrict__ Zh) {
    extern __shared__ char smem[];
    uint32_t sb = smem_u32(smem);
    int tid = threadIdx.x, wid = tid >> 5, lane = tid & 31;
    int bm = blockIdx.x * 256;
    int nb = blockIdx.y;
    int wm = wid >> 1, wn = wid & 1;   // wm 0..7, wn 0..1

    float acc[2][8][4];
    #pragma unroll
    for (int t = 0; t < 2; t++)
        #pragma unroll
        for (int u = 0; u < 8; u++)
            #pragma unroll
            for (int e = 0; e < 4; e++) acc[t][u][e] = 0.f;

    load_chunk_cp(sb, 0, bm, nb, A2, Bp);
    cp_commit();

    for (int ch = 0; ch < 12; ch++) {
        int st = ch & 1;
        if (ch + 1 < 12) {
            load_chunk_cp(sb + (st ^ 1) * GEMM_STAGE, ch + 1, bm, nb, A2, Bp);
            cp_commit();
            cp_wait1();
        } else {
            cp_wait0();
        }
        __syncthreads();

        uint32_t As = sb + st * GEMM_STAGE;
        uint32_t Bs = As + 32768;
        #pragma unroll
        for (int s = 0; s < 4; s++) {
            uint32_t a[2][4], bfrag[4][4];
            #pragma unroll
            for (int t = 0; t < 2; t++) {
                int m_local = wm * 32 + t * 16 + ((lane >> 3) & 1) * 8 + (lane & 7);
                int kseg = s * 2 + (lane >> 4);
                ldmx4(a[t], As + SWZ(m_local * 128 + kseg * 16));
            }
            #pragma unroll
            for (int j = 0; j < 4; j++) {
                int n_local = wn * 64 + (2 * j + (lane >> 4)) * 8 + (lane & 7);
                int kseg = s * 2 + ((lane >> 3) & 1);
                ldmx4(bfrag[j], Bs + SWZ(n_local * 128 + kseg * 16));
            }
            #pragma unroll
            for (int t = 0; t < 2; t++)
                #pragma unroll
                for (int u = 0; u < 8; u++)
                    mma16816(acc[t][u], a[t], bfrag[u >> 1][(u & 1) * 2],
                             bfrag[u >> 1][(u & 1) * 2 + 1]);
        }
        __syncthreads();
    }

    // epilogue (fp16 outputs)
    bool isY = (nb < 2);
    __half* C = isY ? Yh : Zh;
    int colbase = (nb & 1) * 128 + wn * 64;
    #pragma unroll
    for (int t = 0; t < 2; t++) {
        int m0 = bm + wm * 32 + t * 16 + (lane >> 2);
        #pragma unroll
        for (int u = 0; u < 8; u++) {
            int col = colbase + u * 8 + (lane & 3) * 2;
            float v0 = acc[t][u][0], v1 = acc[t][u][1];
            float v2 = acc[t][u][2], v3 = acc[t][u][3];
            if (!isY) {
                float2 bb = *(const float2*)(bias + col);
                v0 += bb.x; v1 += bb.y; v2 += bb.x; v3 += bb.y;
            }
            if (m0 < NN)     *(__half2*)(C + (size_t)m0 * 256 + col)       = __floats2half2_rn(v0, v1);
            if (m0 + 8 < NN) *(__half2*)(C + (size_t)(m0 + 8) * 256 + col) = __floats2half2_rn(v2, v3);
        }
    }
}

// ------ aggregation fused with hi/lo split: out = relu(gather_sum(Yh) + Zh) --
// A2out != nullptr: write bf16 hi/lo (layers 0..4). F32out != nullptr: write fp32 (last layer).
__global__ void aggregate_relu_kernel(const __half* __restrict__ Yh, const __half* __restrict__ Zh,
                                      const int* __restrict__ rowptr, const int* __restrict__ csr,
                                      __nv_bfloat16* __restrict__ A2out, float* __restrict__ F32out,
                                      int n) {
    int warp = (blockIdx.x * blockDim.x + threadIdx.x) >> 5;
    int lane = threadIdx.x & 31;
    if (warp >= n) return;
    int beg = rowptr[warp], end = rowptr[warp + 1];
    size_t off = (size_t)warp * HH + lane * 8;

    float4 acc0, acc1;
    {
        uint4 q = *(const uint4*)(Zh + off);
        float2 f0 = __half22float2(*(__half2*)&q.x);
        float2 f1 = __half22float2(*(__half2*)&q.y);
        float2 f2 = __half22float2(*(__half2*)&q.z);
        float2 f3 = __half22float2(*(__half2*)&q.w);
        acc0 = make_float4(f0.x, f0.y, f1.x, f1.y);
        acc1 = make_float4(f2.x, f2.y, f3.x, f3.y);
    }
    for (int e = beg; e < end; e++) {
        int s0 = csr[e];
        uint4 q = *(const uint4*)(Yh + (size_t)s0 * HH + lane * 8);   // 8 halves
        float2 f0 = __half22float2(*(__half2*)&q.x);
        float2 f1 = __half22float2(*(__half2*)&q.y);
        float2 f2 = __half22float2(*(__half2*)&q.z);
        float2 f3 = __half22float2(*(__half2*)&q.w);
        acc0.x += f0.x; acc0.y += f0.y; acc0.z += f1.x; acc0.w += f1.y;
        acc1.x += f2.x; acc1.y += f2.y; acc1.z += f3.x; acc1.w += f3.y;
    }
    acc0.x = fmaxf(acc0.x, 0.f); acc0.y = fmaxf(acc0.y, 0.f);
    acc0.z = fmaxf(acc0.z, 0.f); acc0.w = fmaxf(acc0.w, 0.f);
    acc1.x = fmaxf(acc1.x, 0.f); acc1.y = fmaxf(acc1.y, 0.f);
    acc1.z = fmaxf(acc1.z, 0.f); acc1.w = fmaxf(acc1.w, 0.f);

    if (F32out) {
        *(float4*)(F32out + off)     = acc0;
        *(float4*)(F32out + off + 4) = acc1;
    }
    if (A2out) {
        float v[8] = {acc0.x, acc0.y, acc0.z, acc0.w, acc1.x, acc1.y, acc1.z, acc1.w};
        __nv_bfloat162 hp[4], lp[4];
        #pragma unroll
        for (int j = 0; j < 4; j++) {
            __nv_bfloat16 h0 = __float2bfloat16(v[2 * j]);
            __nv_bfloat16 h1 = __float2bfloat16(v[2 * j + 1]);
            hp[j] = __nv_bfloat162(h0, h1);
            lp[j] = __nv_bfloat162(__float2bfloat16(v[2 * j]     - __bfloat162float(h0)),
                                   __float2bfloat16(v[2 * j + 1] - __bfloat162float(h1)));
        }
        *(uint4*)(A2out + (size_t)warp * 512 + lane * 8)       = *(uint4*)hp;
        *(uint4*)(A2out + (size_t)warp * 512 + 256 + lane * 8) = *(uint4*)lp;
    }
}

// ---------------- mean pool over sorted batch ids ----------------------------
__device__ __forceinline__ int lower_bound_dev(const int* a, int n, int key) {
    int lo = 0, hi = n;
    while (lo < hi) {
        int mid = (lo + hi) >> 1;
        if (a[mid] < key) lo = mid + 1; else hi = mid;
    }
    return lo;
}

__global__ void pool_kernel(const float* __restrict__ H, const int* __restrict__ batch,
                            float* __restrict__ pooled, int n) {
    int g = blockIdx.x;
    int j = threadIdx.x;  // 256
    __shared__ int s_lo, s_hi;
    if (j == 0) {
        s_lo = lower_bound_dev(batch, n, g);
        s_hi = lower_bound_dev(batch, n, g + 1);
    }
    __syncthreads();
    int lo = s_lo, hi = s_hi;
    float acc = 0.f;
    for (int nd = lo; nd < hi; nd++) acc += H[(size_t)nd * HH + j];
    int cnt = hi - lo;
    pooled[g * HH + j] = acc / (float)max(cnt, 1);
}

// ---------------- output head ------------------------------------------------
__global__ void head_kernel(const float* __restrict__ pooled, const float* __restrict__ w_out,
                            const float* __restrict__ b_out, float* __restrict__ out) {
    int g = blockIdx.x;
    int j = threadIdx.x;  // 32, guard 24
    if (j >= OUTD) return;
    float acc = b_out[j];
    #pragma unroll 8
    for (int k = 0; k < HH; k++)
        acc += pooled[g * HH + k] * w_out[k * OUTD + j];
    out[g * OUTD + j] = acc;
}

// ---------------- launch -----------------------------------------------------
extern "C" void kernel_launch(void* const* d_in, const int* in_sizes, int n_in,
                              void* d_out, int out_size) {
    const float* x       = (const float*)d_in[0];
    const int*   ei      = (const int*)d_in[1];
    const int*   batch   = (const int*)d_in[2];
    const float* w_rel1  = (const float*)d_in[3];
    const float* w_root1 = (const float*)d_in[4];
    const float* b1      = (const float*)d_in[5];
    const float* w_rel   = (const float*)d_in[6];   // 6 x 256 x 256
    const float* w_root  = (const float*)d_in[7];
    const float* b       = (const float*)d_in[8];   // 6 x 256
    const float* w_out   = (const float*)d_in[9];
    const float* b_out   = (const float*)d_in[10];
    float* out = (float*)d_out;

    const int* src = ei;        // edge_index[0]
    const int* dst = ei + EE;   // edge_index[1]

    float *hf, *agg3, *pooled;
    __half *yh, *zh;
    int *deg, *rowptr, *cursor, *csr, *bsums;
    __nv_bfloat16 *A2, *Bp;
    cudaGetSymbolAddress((void**)&hf, g_hf);
    cudaGetSymbolAddress((void**)&yh, g_yh);
    cudaGetSymbolAddress((void**)&zh, g_zh);
    cudaGetSymbolAddress((void**)&agg3, g_agg3);
    cudaGetSymbolAddress((void**)&pooled, g_pooled);
    cudaGetSymbolAddress((void**)&deg, g_deg);
    cudaGetSymbolAddress((void**)&rowptr, g_rowptr);
    cudaGetSymbolAddress((void**)&cursor, g_cursor);
    cudaGetSymbolAddress((void**)&csr, g_csr);
    cudaGetSymbolAddress((void**)&bsums, g_bsums);
    cudaGetSymbolAddress((void**)&A2, g_A2);
    cudaGetSymbolAddress((void**)&Bp, g_Bp);

    cudaFuncSetAttribute(gemm_tc_kernel, cudaFuncAttributeMaxDynamicSharedMemorySize, GEMM_SMEM_TOTAL);

    // ---- build CSR (once per launch) ----
    zero_int_kernel<<<(NN + 255) / 256, 256>>>(deg, NN);
    zero_int_kernel<<<(NN + 255) / 256, 256>>>(cursor, NN);
    count_deg_kernel<<<(EE + 255) / 256, 256>>>(dst, deg, EE);
    scan_pass1<<<SCAN_BLOCKS, 256>>>(deg, bsums, NN);
    scan_pass2<<<1, 256>>>(bsums, SCAN_BLOCKS);
    scan_pass3<<<SCAN_BLOCKS, 256>>>(deg, bsums, rowptr, NN);
    fill_csr_kernel<<<(EE + 255) / 256, 256>>>(src, dst, rowptr, cursor, csr, EE);

    // ---- weight prep (hi/lo split, K-concat layout) ----
    prep_weights_kernel<<<(6 * 512 * 256 + 255) / 256, 256>>>(w_rel, w_root, Bp);

    // ---- layer 1 (3 -> 256), fp32 -> A2 hi/lo directly ----
    aggx_kernel<<<(NN + 255) / 256, 256>>>(x, rowptr, csr, agg3, NN);
    layer1_kernel<<<NN, 256>>>(x, agg3, w_rel1, w_root1, b1, A2);

    // ---- layers 2..7 (256 -> 256), tensor cores via mma.sync, fused convert --
    dim3 ggrid(NPAD / 256, 4);
    for (int i = 0; i < 6; i++) {
        gemm_tc_kernel<<<ggrid, 512, GEMM_SMEM_TOTAL>>>(A2, Bp + (size_t)i * 512 * 768,
                                                        b + i * HH, yh, zh);
        bool last = (i == 5);
        aggregate_relu_kernel<<<(NN * 32 + 255) / 256, 256>>>(
            yh, zh, rowptr, csr,
            last ? (__nv_bfloat16*)nullptr : A2,
            last ? hf : (float*)nullptr, NN);
    }

    // ---- pool + head ----
    pool_kernel<<<GG, 256>>>(hf, batch, pooled, NN);
    head_kernel<<<GG, 32>>>(pooled, w_out, b_out, out);
}

// round 9
// speedup vs baseline: 1.1293x; 1.1293x over previous
#include <cuda_runtime.h>
#include <cuda_bf16.h>
#include <cuda_fp16.h>
#include <cstdint>

// Problem constants (fixed by the dataset)
#define NN   50000
#define NPAD 50048        // 391 * 128
#define EE   800000
#define FIN  3
#define HH   256
#define GG   64
#define OUTD 24

// ---------------- scratch (device globals; no allocation allowed) -----------
__device__ float g_hf[NN * HH];           // final-layer fp32 activations (for pooling)
__device__ __half g_yh[(size_t)NN * HH];  // h @ w_rel, fp16 (gather payload)
__device__ __half g_zh[(size_t)NN * HH];  // h @ w_root + b, fp16
__device__ float g_agg3[NN * FIN];
__device__ float g_pooled[GG * HH];
__device__ int   g_deg[NN + 1];
__device__ int   g_rowptr[NN + 1];
__device__ int   g_cursor[NN + 1];
__device__ int   g_csr[EE];
__device__ int   g_bsums[256];
// tensor-core path scratch
__device__ __nv_bfloat16 g_A2[(size_t)NPAD * 512];      // [row][0..255]=hi, [256..511]=lo (pad rows: zero)
__device__ __nv_bfloat16 g_Bp[(size_t)6 * 512 * 768];   // per layer: [n(512)][k'(768)] = [hi|hi|lo]

// ---------------- PTX helpers (family-safe only: mma.sync / ldmatrix / cp.async)
__device__ __forceinline__ uint32_t smem_u32(const void* p) {
    uint32_t a;
    asm("{ .reg .u64 t; cvta.to.shared.u64 t, %1; cvt.u32.u64 %0, t; }" : "=r"(a) : "l"(p));
    return a;
}
__device__ __forceinline__ void cp16(uint32_t saddr, const void* gptr) {
    asm volatile("cp.async.cg.shared.global [%0], [%1], 16;" :: "r"(saddr), "l"(gptr) : "memory");
}
__device__ __forceinline__ void cp_commit() {
    asm volatile("cp.async.commit_group;" ::: "memory");
}
__device__ __forceinline__ void cp_wait1() {
    asm volatile("cp.async.wait_group 1;" ::: "memory");
}
__device__ __forceinline__ void cp_wait0() {
    asm volatile("cp.async.wait_group 0;" ::: "memory");
}
__device__ __forceinline__ void ldmx4(uint32_t* r, uint32_t addr) {
    asm volatile("ldmatrix.sync.aligned.m8n8.x4.shared.b16 {%0,%1,%2,%3}, [%4];"
                 : "=r"(r[0]), "=r"(r[1]), "=r"(r[2]), "=r"(r[3]) : "r"(addr));
}
__device__ __forceinline__ void mma16816(float* c, const uint32_t* a, uint32_t b0, uint32_t b1) {
    asm volatile(
        "mma.sync.aligned.m16n8k16.row.col.f32.bf16.bf16.f32 "
        "{%0,%1,%2,%3}, {%4,%5,%6,%7}, {%8,%9}, {%0,%1,%2,%3};"
        : "+f"(c[0]), "+f"(c[1]), "+f"(c[2]), "+f"(c[3])
        : "r"(a[0]), "r"(a[1]), "r"(a[2]), "r"(a[3]), "r"(b0), "r"(b1));
}
// 128B-atom XOR swizzle (bank-conflict-free STS/ldmatrix)
__device__ __forceinline__ uint32_t SWZ(uint32_t x) { return x ^ ((x >> 3) & 0x70); }

// ---------------- CSR construction ------------------------------------------
__global__ void zero_int_kernel(int* a, int n) {
    int i = blockIdx.x * blockDim.x + threadIdx.x;
    if (i < n) a[i] = 0;
}

__global__ void count_deg_kernel(const int* __restrict__ dst, int* __restrict__ deg, int e) {
    int i = blockIdx.x * blockDim.x + threadIdx.x;
    if (i < e) atomicAdd(&deg[dst[i]], 1);
}

// ---- parallel exclusive scan over NN elems: 3 phases, 256-elem blocks ----
#define SCAN_BLOCKS ((NN + 255) / 256)   // 196

__global__ void scan_pass1(const int* __restrict__ deg, int* __restrict__ bsums, int n) {
    int i = blockIdx.x * 256 + threadIdx.x;
    int v = (i < n) ? deg[i] : 0;
    #pragma unroll
    for (int o = 16; o > 0; o >>= 1) v += __shfl_down_sync(0xFFFFFFFF, v, o);
    __shared__ int ws[8];
    int wid = threadIdx.x >> 5, lane = threadIdx.x & 31;
    if (lane == 0) ws[wid] = v;
    __syncthreads();
    if (threadIdx.x == 0) {
        int s = 0;
        #pragma unroll
        for (int w = 0; w < 8; w++) s += ws[w];
        bsums[blockIdx.x] = s;
    }
}

__global__ void scan_pass2(int* __restrict__ bsums, int nb) {
    __shared__ int sh[256];
    int tid = threadIdx.x;
    int v = (tid < nb) ? bsums[tid] : 0;
    sh[tid] = v;
    __syncthreads();
    #pragma unroll
    for (int off = 1; off < 256; off <<= 1) {
        int t = (tid >= off) ? sh[tid - off] : 0;
        __syncthreads();
        sh[tid] += t;
        __syncthreads();
    }
    if (tid < nb) bsums[tid] = sh[tid] - v;   // exclusive
}

__global__ void scan_pass3(const int* __restrict__ deg, const int* __restrict__ bsums,
                           int* __restrict__ rowptr, int n) {
    __shared__ int sh[256];
    int i = blockIdx.x * 256 + threadIdx.x;
    int tid = threadIdx.x;
    int v = (i < n) ? deg[i] : 0;
    sh[tid] = v;
    __syncthreads();
    #pragma unroll
    for (int off = 1; off < 256; off <<= 1) {
        int t = (tid >= off) ? sh[tid - off] : 0;
        __syncthreads();
        sh[tid] += t;
        __syncthreads();
    }
    int incl = sh[tid];
    int base = bsums[blockIdx.x];
    if (i < n)  rowptr[i] = base + incl - v;
    if (i == n - 1) rowptr[n] = base + incl;
}

__global__ void fill_csr_kernel(const int* __restrict__ src, const int* __restrict__ dst,
                                const int* __restrict__ rowptr, int* __restrict__ cursor,
                                int* __restrict__ csr, int e) {
    int i = blockIdx.x * blockDim.x + threadIdx.x;
    if (i < e) {
        int d = dst[i];
        int pos = atomicAdd(&cursor[d], 1);
        csr[rowptr[d] + pos] = src[i];
    }
}

// ---------------- layer 1 (F_IN=3 -> H), writes A2 hi/lo directly ------------
__global__ void aggx_kernel(const float* __restrict__ x,
                            const int* __restrict__ rowptr, const int* __restrict__ csr,
                            float* __restrict__ agg3, int n) {
    int i = blockIdx.x * blockDim.x + threadIdx.x;
    if (i >= n) return;
    float a0 = 0.f, a1 = 0.f, a2 = 0.f;
    int beg = rowptr[i], end = rowptr[i + 1];
    for (int e = beg; e < end; e++) {
        int s = csr[e];
        a0 += x[s * 3 + 0];
        a1 += x[s * 3 + 1];
        a2 += x[s * 3 + 2];
    }
    agg3[i * 3 + 0] = a0;
    agg3[i * 3 + 1] = a1;
    agg3[i * 3 + 2] = a2;
}

__global__ void layer1_kernel(const float* __restrict__ x, const float* __restrict__ agg3,
                              const float* __restrict__ wr, const float* __restrict__ wro,
                              const float* __restrict__ b1, __nv_bfloat16* __restrict__ A2) {
    int n = blockIdx.x;
    int j = threadIdx.x;  // 256
    __shared__ float sx[3], sa[3];
    if (j < 3) { sx[j] = x[n * 3 + j]; sa[j] = agg3[n * 3 + j]; }
    __syncthreads();
    float v = b1[j];
    #pragma unroll
    for (int f = 0; f < 3; f++)
        v += sa[f] * wr[f * HH + j] + sx[f] * wro[f * HH + j];
    v = fmaxf(v, 0.f);
    __nv_bfloat16 hi = __float2bfloat16(v);
    __nv_bfloat16 lo = __float2bfloat16(v - __bfloat162float(hi));
    A2[(size_t)n * 512 + j]       = hi;
    A2[(size_t)n * 512 + 256 + j] = lo;
}

// ---------------- weight prep: fp32 [K,N] -> bf16 hi/lo, [N][768] K-major ----
__global__ void prep_weights_kernel(const float* __restrict__ w_rel, const float* __restrict__ w_root,
                                    __nv_bfloat16* __restrict__ Bp) {
    int idx = blockIdx.x * blockDim.x + threadIdx.x;
    if (idx >= 6 * 512 * 256) return;
    int k = idx & 255;
    int n = (idx >> 8) & 511;
    int L = idx >> 17;
    float w = (n < 256) ? w_rel[(size_t)L * 65536 + k * 256 + n]
                        : w_root[(size_t)L * 65536 + k * 256 + (n - 256)];
    __nv_bfloat16 hi = __float2bfloat16(w);
    __nv_bfloat16 lo = __float2bfloat16(w - __bfloat162float(hi));
    __nv_bfloat16* bp = Bp + (size_t)L * 512 * 768 + (size_t)n * 768;
    bp[k]       = hi;
    bp[256 + k] = hi;
    bp[512 + k] = lo;
}

// ---------------- mma.sync GEMM ----------------------------------------------
// C[128,128] per CTA; C = A'[M,768] x B'^T, A' chunks (hi,lo,hi) vs B' (hi,hi,lo).
// grid (391, 4): blockIdx.y 0,1 -> Yh cols 0/128; 2,3 -> Zh cols 0/128 (+bias).
// 8 warps: wm = wid>>1 (4 x 32 rows), wn = wid&1 (2 x 64 cols).
// SMEM: 2 stages x (A 16KB + B 16KB) = 64KB, cp.async double-buffered.
#define GEMM_SMEM_TOTAL (2 * 32768)

__device__ __forceinline__ void load_chunk_cp(uint32_t sdst, int c, int bm, int nb,
                                              const __nv_bfloat16* __restrict__ A2,
                                              const __nv_bfloat16* __restrict__ Bp) {
    int tid = threadIdx.x;
    int kmap = (c < 8) ? c * 64 : (c - 8) * 64;   // A chunks: 0-3 hi, 4-7 lo, 8-11 hi
    #pragma unroll
    for (int i = 0; i < 4; i++) {                  // A: 128 rows x 128B
        int v = tid + i * 256;
        int r = v >> 3, kc = v & 7;
        const void* g = A2 + (size_t)(bm + r) * 512 + kmap + kc * 8;
        cp16(sdst + SWZ(r * 128 + kc * 16), g);
    }
    uint32_t bdst = sdst + 16384;
    #pragma unroll
    for (int i = 0; i < 4; i++) {                  // B: 128 n-rows x 128B
        int v = tid + i * 256;
        int r = v >> 3, kc = v & 7;
        const void* g = Bp + (size_t)(nb * 128 + r) * 768 + c * 64 + kc * 8;
        cp16(bdst + SWZ(r * 128 + kc * 16), g);
    }
}

__global__ __launch_bounds__(256)
void gemm_tc_kernel(const __nv_bfloat16* __restrict__ A2, const __nv_bfloat16* __restrict__ Bp,
                    const float* __restrict__ bias, __half* __restrict__ Yh, __half* __restrict__ Zh) {
    extern __shared__ char smem[];
    uint32_t sb = smem_u32(smem);
    int tid = threadIdx.x, wid = tid >> 5, lane = tid & 31;
    int bm = blockIdx.x * 128;
    int nb = blockIdx.y;
    int wm = wid >> 1, wn = wid & 1;

    float acc[2][8][4];
    #pragma unroll
    for (int t = 0; t < 2; t++)
        #pragma unroll
        for (int u = 0; u < 8; u++)
            #pragma unroll
            for (int e = 0; e < 4; e++) acc[t][u][e] = 0.f;

    load_chunk_cp(sb, 0, bm, nb, A2, Bp);
    cp_commit();

    for (int ch = 0; ch < 12; ch++) {
        int st = ch & 1;
        if (ch + 1 < 12) {
            load_chunk_cp(sb + (st ^ 1) * 32768, ch + 1, bm, nb, A2, Bp);
            cp_commit();
            cp_wait1();
        } else {
            cp_wait0();
        }
        __syncthreads();

        uint32_t As = sb + st * 32768;
        uint32_t Bs = As + 16384;
        #pragma unroll
        for (int s = 0; s < 4; s++) {
            uint32_t a[2][4], bfrag[4][4];
            #pragma unroll
            for (int t = 0; t < 2; t++) {
                int m_local = wm * 32 + t * 16 + ((lane >> 3) & 1) * 8 + (lane & 7);
                int kseg = s * 2 + (lane >> 4);
                ldmx4(a[t], As + SWZ(m_local * 128 + kseg * 16));
            }
            #pragma unroll
            for (int j = 0; j < 4; j++) {
                int n_local = wn * 64 + (2 * j + (lane >> 4)) * 8 + (lane & 7);
                int kseg = s * 2 + ((lane >> 3) & 1);
                ldmx4(bfrag[j], Bs + SWZ(n_local * 128 + kseg * 16));
            }
            #pragma unroll
            for (int t = 0; t < 2; t++)
                #pragma unroll
                for (int u = 0; u < 8; u++)
                    mma16816(acc[t][u], a[t], bfrag[u >> 1][(u & 1) * 2],
                             bfrag[u >> 1][(u & 1) * 2 + 1]);
        }
        __syncthreads();
    }

    // epilogue (fp16 outputs)
    bool isY = (nb < 2);
    __half* C = isY ? Yh : Zh;
    int colbase = (nb & 1) * 128 + wn * 64;
    #pragma unroll
    for (int t = 0; t < 2; t++) {
        int m0 = bm + wm * 32 + t * 16 + (lane >> 2);
        #pragma unroll
        for (int u = 0; u < 8; u++) {
            int col = colbase + u * 8 + (lane & 3) * 2;
            float v0 = acc[t][u][0], v1 = acc[t][u][1];
            float v2 = acc[t][u][2], v3 = acc[t][u][3];
            if (!isY) {
                float2 bb = *(const float2*)(bias + col);
                v0 += bb.x; v1 += bb.y; v2 += bb.x; v3 += bb.y;
            }
            if (m0 < NN)     *(__half2*)(C + (size_t)m0 * 256 + col)       = __floats2half2_rn(v0, v1);
            if (m0 + 8 < NN) *(__half2*)(C + (size_t)(m0 + 8) * 256 + col) = __floats2half2_rn(v2, v3);
        }
    }
}

// ------ aggregation fused with hi/lo split: out = relu(gather_sum(Yh) + Zh) --
// A2out != nullptr: write bf16 hi/lo (layers 0..4). F32out != nullptr: write fp32 (last layer).
__global__ void aggregate_relu_kernel(const __half* __restrict__ Yh, const __half* __restrict__ Zh,
                                      const int* __restrict__ rowptr, const int* __restrict__ csr,
                                      __nv_bfloat16* __restrict__ A2out, float* __restrict__ F32out,
                                      int n) {
    int warp = (blockIdx.x * blockDim.x + threadIdx.x) >> 5;
    int lane = threadIdx.x & 31;
    if (warp >= n) return;
    int beg = rowptr[warp], end = rowptr[warp + 1];
    size_t off = (size_t)warp * HH + lane * 8;

    float4 acc0, acc1;
    {
        uint4 q = *(const uint4*)(Zh + off);
        float2 f0 = __half22float2(*(__half2*)&q.x);
        float2 f1 = __half22float2(*(__half2*)&q.y);
        float2 f2 = __half22float2(*(__half2*)&q.z);
        float2 f3 = __half22float2(*(__half2*)&q.w);
        acc0 = make_float4(f0.x, f0.y, f1.x, f1.y);
        acc1 = make_float4(f2.x, f2.y, f3.x, f3.y);
    }
    for (int e = beg; e < end; e++) {
        int s0 = csr[e];
        uint4 q = *(const uint4*)(Yh + (size_t)s0 * HH + lane * 8);   // 8 halves
        float2 f0 = __half22float2(*(__half2*)&q.x);
        float2 f1 = __half22float2(*(__half2*)&q.y);
        float2 f2 = __half22float2(*(__half2*)&q.z);
        float2 f3 = __half22float2(*(__half2*)&q.w);
        acc0.x += f0.x; acc0.y += f0.y; acc0.z += f1.x; acc0.w += f1.y;
        acc1.x += f2.x; acc1.y += f2.y; acc1.z += f3.x; acc1.w += f3.y;
    }
    acc0.x = fmaxf(acc0.x, 0.f); acc0.y = fmaxf(acc0.y, 0.f);
    acc0.z = fmaxf(acc0.z, 0.f); acc0.w = fmaxf(acc0.w, 0.f);
    acc1.x = fmaxf(acc1.x, 0.f); acc1.y = fmaxf(acc1.y, 0.f);
    acc1.z = fmaxf(acc1.z, 0.f); acc1.w = fmaxf(acc1.w, 0.f);

    if (F32out) {
        *(float4*)(F32out + off)     = acc0;
        *(float4*)(F32out + off + 4) = acc1;
    }
    if (A2out) {
        float v[8] = {acc0.x, acc0.y, acc0.z, acc0.w, acc1.x, acc1.y, acc1.z, acc1.w};
        __nv_bfloat162 hp[4], lp[4];
        #pragma unroll
        for (int j = 0; j < 4; j++) {
            __nv_bfloat16 h0 = __float2bfloat16(v[2 * j]);
            __nv_bfloat16 h1 = __float2bfloat16(v[2 * j + 1]);
            hp[j] = __nv_bfloat162(h0, h1);
            lp[j] = __nv_bfloat162(__float2bfloat16(v[2 * j]     - __bfloat162float(h0)),
                                   __float2bfloat16(v[2 * j + 1] - __bfloat162float(h1)));
        }
        *(uint4*)(A2out + (size_t)warp * 512 + lane * 8)       = *(uint4*)hp;
        *(uint4*)(A2out + (size_t)warp * 512 + 256 + lane * 8) = *(uint4*)lp;
    }
}

// ---------------- mean pool over sorted batch ids ----------------------------
__device__ __forceinline__ int lower_bound_dev(const int* a, int n, int key) {
    int lo = 0, hi = n;
    while (lo < hi) {
        int mid = (lo + hi) >> 1;
        if (a[mid] < key) lo = mid + 1; else hi = mid;
    }
    return lo;
}

__global__ void pool_kernel(const float* __restrict__ H, const int* __restrict__ batch,
                            float* __restrict__ pooled, int n) {
    int g = blockIdx.x;
    int j = threadIdx.x;  // 256
    __shared__ int s_lo, s_hi;
    if (j == 0) {
        s_lo = lower_bound_dev(batch, n, g);
        s_hi = lower_bound_dev(batch, n, g + 1);
    }
    __syncthreads();
    int lo = s_lo, hi = s_hi;
    float acc = 0.f;
    for (int nd = lo; nd < hi; nd++) acc += H[(size_t)nd * HH + j];
    int cnt = hi - lo;
    pooled[g * HH + j] = acc / (float)max(cnt, 1);
}

// ---------------- output head ------------------------------------------------
__global__ void head_kernel(const float* __restrict__ pooled, const float* __restrict__ w_out,
                            const float* __restrict__ b_out, float* __restrict__ out) {
    int g = blockIdx.x;
    int j = threadIdx.x;  // 32, guard 24
    if (j >= OUTD) return;
    float acc = b_out[j];
    #pragma unroll 8
    for (int k = 0; k < HH; k++)
        acc += pooled[g * HH + k] * w_out[k * OUTD + j];
    out[g * OUTD + j] = acc;
}

// ---------------- launch -----------------------------------------------------
extern "C" void kernel_launch(void* const* d_in, const int* in_sizes, int n_in,
                              void* d_out, int out_size) {
    const float* x       = (const float*)d_in[0];
    const int*   ei      = (const int*)d_in[1];
    const int*   batch   = (const int*)d_in[2];
    const float* w_rel1  = (const float*)d_in[3];
    const float* w_root1 = (const float*)d_in[4];
    const float* b1      = (const float*)d_in[5];
    const float* w_rel   = (const float*)d_in[6];   // 6 x 256 x 256
    const float* w_root  = (const float*)d_in[7];
    const float* b       = (const float*)d_in[8];   // 6 x 256
    const float* w_out   = (const float*)d_in[9];
    const float* b_out   = (const float*)d_in[10];
    float* out = (float*)d_out;

    const int* src = ei;        // edge_index[0]
    const int* dst = ei + EE;   // edge_index[1]

    float *hf, *agg3, *pooled;
    __half *yh, *zh;
    int *deg, *rowptr, *cursor, *csr, *bsums;
    __nv_bfloat16 *A2, *Bp;
    cudaGetSymbolAddress((void**)&hf, g_hf);
    cudaGetSymbolAddress((void**)&yh, g_yh);
    cudaGetSymbolAddress((void**)&zh, g_zh);
    cudaGetSymbolAddress((void**)&agg3, g_agg3);
    cudaGetSymbolAddress((void**)&pooled, g_pooled);
    cudaGetSymbolAddress((void**)&deg, g_deg);
    cudaGetSymbolAddress((void**)&rowptr, g_rowptr);
    cudaGetSymbolAddress((void**)&cursor, g_cursor);
    cudaGetSymbolAddress((void**)&csr, g_csr);
    cudaGetSymbolAddress((void**)&bsums, g_bsums);
    cudaGetSymbolAddress((void**)&A2, g_A2);
    cudaGetSymbolAddress((void**)&Bp, g_Bp);

    cudaFuncSetAttribute(gemm_tc_kernel, cudaFuncAttributeMaxDynamicSharedMemorySize, GEMM_SMEM_TOTAL);

    // ---- build CSR (once per launch) ----
    zero_int_kernel<<<(NN + 255) / 256, 256>>>(deg, NN);
    zero_int_kernel<<<(NN + 255) / 256, 256>>>(cursor, NN);
    count_deg_kernel<<<(EE + 255) / 256, 256>>>(dst, deg, EE);
    scan_pass1<<<SCAN_BLOCKS, 256>>>(deg, bsums, NN);
    scan_pass2<<<1, 256>>>(bsums, SCAN_BLOCKS);
    scan_pass3<<<SCAN_BLOCKS, 256>>>(deg, bsums, rowptr, NN);
    fill_csr_kernel<<<(EE + 255) / 256, 256>>>(src, dst, rowptr, cursor, csr, EE);

    // ---- weight prep (hi/lo split, K-concat layout) ----
    prep_weights_kernel<<<(6 * 512 * 256 + 255) / 256, 256>>>(w_rel, w_root, Bp);

    // ---- layer 1 (3 -> 256), fp32 -> A2 hi/lo directly ----
    aggx_kernel<<<(NN + 255) / 256, 256>>>(x, rowptr, csr, agg3, NN);
    layer1_kernel<<<NN, 256>>>(x, agg3, w_rel1, w_root1, b1, A2);

    // ---- layers 2..7 (256 -> 256), tensor cores via mma.sync, fused convert --
    dim3 ggrid(NPAD / 128, 4);
    for (int i = 0; i < 6; i++) {
        gemm_tc_kernel<<<ggrid, 256, GEMM_SMEM_TOTAL>>>(A2, Bp + (size_t)i * 512 * 768,
                                                        b + i * HH, yh, zh);
        bool last = (i == 5);
        aggregate_relu_kernel<<<(NN * 32 + 255) / 256, 256>>>(
            yh, zh, rowptr, csr,
            last ? (__nv_bfloat16*)nullptr : A2,
            last ? hf : (float*)nullptr, NN);
    }

    // ---- pool + head ----
    pool_kernel<<<GG, 256>>>(hf, batch, pooled, NN);
    head_kernel<<<GG, 32>>>(pooled, w_out, b_out, out);
}

// round 10
// speedup vs baseline: 1.7835x; 1.5793x over previous
#include <cuda_runtime.h>
#include <cuda_bf16.h>
#include <cuda_fp16.h>
#include <cstdint>

// Problem constants (fixed by the dataset)
#define NN   50000
#define NPAD 50048        // 391 * 128
#define EE   800000
#define FIN  3
#define HH   256
#define GG   64
#define OUTD 24

// ---------------- scratch (device globals; no allocation allowed) -----------
__device__ float g_hf[NN * HH];           // final-layer fp32 activations (for pooling)
__device__ __half g_yh[(size_t)NN * HH];  // h @ w_rel, fp16 (gather payload)
__device__ __half g_zh[(size_t)NN * HH];  // h @ w_root + b, fp16
__device__ float g_agg3[NN * FIN];
__device__ float g_pooled[GG * HH];
__device__ int   g_deg[NN + 1];
__device__ int   g_rowptr[NN + 1];
__device__ int   g_cursor[NN + 1];
__device__ int   g_csr[EE];
__device__ int   g_bsums[256];
// tensor-core path scratch (single fp16, no hi/lo split)
__device__ __half g_Ah[(size_t)NPAD * 256];            // activations, fp16 (pad rows: zero)
__device__ __half g_Bh[(size_t)6 * 512 * 256];         // per layer: [n(512)][k(256)] fp16, K-major

// ---------------- PTX helpers (family-safe only: mma.sync / ldmatrix / cp.async)
__device__ __forceinline__ uint32_t smem_u32(const void* p) {
    uint32_t a;
    asm("{ .reg .u64 t; cvta.to.shared.u64 t, %1; cvt.u32.u64 %0, t; }" : "=r"(a) : "l"(p));
    return a;
}
__device__ __forceinline__ void cp16(uint32_t saddr, const void* gptr) {
    asm volatile("cp.async.cg.shared.global [%0], [%1], 16;" :: "r"(saddr), "l"(gptr) : "memory");
}
__device__ __forceinline__ void cp_commit() {
    asm volatile("cp.async.commit_group;" ::: "memory");
}
__device__ __forceinline__ void cp_wait1() {
    asm volatile("cp.async.wait_group 1;" ::: "memory");
}
__device__ __forceinline__ void cp_wait0() {
    asm volatile("cp.async.wait_group 0;" ::: "memory");
}
__device__ __forceinline__ void ldmx4(uint32_t* r, uint32_t addr) {
    asm volatile("ldmatrix.sync.aligned.m8n8.x4.shared.b16 {%0,%1,%2,%3}, [%4];"
                 : "=r"(r[0]), "=r"(r[1]), "=r"(r[2]), "=r"(r[3]) : "r"(addr));
}
__device__ __forceinline__ void mma16816(float* c, const uint32_t* a, uint32_t b0, uint32_t b1) {
    asm volatile(
        "mma.sync.aligned.m16n8k16.row.col.f32.f16.f16.f32 "
        "{%0,%1,%2,%3}, {%4,%5,%6,%7}, {%8,%9}, {%0,%1,%2,%3};"
        : "+f"(c[0]), "+f"(c[1]), "+f"(c[2]), "+f"(c[3])
        : "r"(a[0]), "r"(a[1]), "r"(a[2]), "r"(a[3]), "r"(b0), "r"(b1));
}
// 128B-atom XOR swizzle (bank-conflict-free STS/ldmatrix)
__device__ __forceinline__ uint32_t SWZ(uint32_t x) { return x ^ ((x >> 3) & 0x70); }

// ---------------- CSR construction ------------------------------------------
__global__ void zero_int_kernel(int* a, int n) {
    int i = blockIdx.x * blockDim.x + threadIdx.x;
    if (i < n) a[i] = 0;
}

__global__ void count_deg_kernel(const int* __restrict__ dst, int* __restrict__ deg, int e) {
    int i = blockIdx.x * blockDim.x + threadIdx.x;
    if (i < e) atomicAdd(&deg[dst[i]], 1);
}

// ---- parallel exclusive scan over NN elems: 3 phases, 256-elem blocks ----
#define SCAN_BLOCKS ((NN + 255) / 256)   // 196

__global__ void scan_pass1(const int* __restrict__ deg, int* __restrict__ bsums, int n) {
    int i = blockIdx.x * 256 + threadIdx.x;
    int v = (i < n) ? deg[i] : 0;
    #pragma unroll
    for (int o = 16; o > 0; o >>= 1) v += __shfl_down_sync(0xFFFFFFFF, v, o);
    __shared__ int ws[8];
    int wid = threadIdx.x >> 5, lane = threadIdx.x & 31;
    if (lane == 0) ws[wid] = v;
    __syncthreads();
    if (threadIdx.x == 0) {
        int s = 0;
        #pragma unroll
        for (int w = 0; w < 8; w++) s += ws[w];
        bsums[blockIdx.x] = s;
    }
}

__global__ void scan_pass2(int* __restrict__ bsums, int nb) {
    __shared__ int sh[256];
    int tid = threadIdx.x;
    int v = (tid < nb) ? bsums[tid] : 0;
    sh[tid] = v;
    __syncthreads();
    #pragma unroll
    for (int off = 1; off < 256; off <<= 1) {
        int t = (tid >= off) ? sh[tid - off] : 0;
        __syncthreads();
        sh[tid] += t;
        __syncthreads();
    }
    if (tid < nb) bsums[tid] = sh[tid] - v;   // exclusive
}

__global__ void scan_pass3(const int* __restrict__ deg, const int* __restrict__ bsums,
                           int* __restrict__ rowptr, int n) {
    __shared__ int sh[256];
    int i = blockIdx.x * 256 + threadIdx.x;
    int tid = threadIdx.x;
    int v = (i < n) ? deg[i] : 0;
    sh[tid] = v;
    __syncthreads();
    #pragma unroll
    for (int off = 1; off < 256; off <<= 1) {
        int t = (tid >= off) ? sh[tid - off] : 0;
        __syncthreads();
        sh[tid] += t;
        __syncthreads();
    }
    int incl = sh[tid];
    int base = bsums[blockIdx.x];
    if (i < n)  rowptr[i] = base + incl - v;
    if (i == n - 1) rowptr[n] = base + incl;
}

__global__ void fill_csr_kernel(const int* __restrict__ src, const int* __restrict__ dst,
                                const int* __restrict__ rowptr, int* __restrict__ cursor,
                                int* __restrict__ csr, int e) {
    int i = blockIdx.x * blockDim.x + threadIdx.x;
    if (i < e) {
        int d = dst[i];
        int pos = atomicAdd(&cursor[d], 1);
        csr[rowptr[d] + pos] = src[i];
    }
}

// ---------------- layer 1 (F_IN=3 -> H), writes Ah fp16 directly -------------
__global__ void aggx_kernel(const float* __restrict__ x,
                            const int* __restrict__ rowptr, const int* __restrict__ csr,
                            float* __restrict__ agg3, int n) {
    int i = blockIdx.x * blockDim.x + threadIdx.x;
    if (i >= n) return;
    float a0 = 0.f, a1 = 0.f, a2 = 0.f;
    int beg = rowptr[i], end = rowptr[i + 1];
    for (int e = beg; e < end; e++) {
        int s = csr[e];
        a0 += x[s * 3 + 0];
        a1 += x[s * 3 + 1];
        a2 += x[s * 3 + 2];
    }
    agg3[i * 3 + 0] = a0;
    agg3[i * 3 + 1] = a1;
    agg3[i * 3 + 2] = a2;
}

__global__ void layer1_kernel(const float* __restrict__ x, const float* __restrict__ agg3,
                              const float* __restrict__ wr, const float* __restrict__ wro,
                              const float* __restrict__ b1, __half* __restrict__ Ah) {
    int n = blockIdx.x;
    int j = threadIdx.x;  // 256
    __shared__ float sx[3], sa[3];
    if (j < 3) { sx[j] = x[n * 3 + j]; sa[j] = agg3[n * 3 + j]; }
    __syncthreads();
    float v = b1[j];
    #pragma unroll
    for (int f = 0; f < 3; f++)
        v += sa[f] * wr[f * HH + j] + sx[f] * wro[f * HH + j];
    v = fmaxf(v, 0.f);
    Ah[(size_t)n * 256 + j] = __float2half_rn(v);
}

// ---------------- weight prep: fp32 [K,N] -> fp16 [N][256] K-major -----------
__global__ void prep_weights_kernel(const float* __restrict__ w_rel, const float* __restrict__ w_root,
                                    __half* __restrict__ Bh) {
    int idx = blockIdx.x * blockDim.x + threadIdx.x;
    if (idx >= 6 * 512 * 256) return;
    int k = idx & 255;
    int n = (idx >> 8) & 511;
    int L = idx >> 17;
    float w = (n < 256) ? w_rel[(size_t)L * 65536 + k * 256 + n]
                        : w_root[(size_t)L * 65536 + k * 256 + (n - 256)];
    Bh[(size_t)L * 512 * 256 + (size_t)n * 256 + k] = __float2half_rn(w);
}

// ---------------- mma.sync GEMM ----------------------------------------------
// C[128,128] per CTA; C = A[M,256] x B^T (fp16 in, fp32 acc, fp16 out).
// grid (391, 4): blockIdx.y 0,1 -> Yh cols 0/128; 2,3 -> Zh cols 0/128 (+bias).
// 8 warps: wm = wid>>1 (4 x 32 rows), wn = wid&1 (2 x 64 cols).
// K = 256 = 4 chunks of 64; SMEM: 2 stages x (A 16KB + B 16KB) = 64KB.
#define GEMM_SMEM_TOTAL (2 * 32768)
#define K_CHUNKS 4

__device__ __forceinline__ void load_chunk_cp(uint32_t sdst, int c, int bm, int nb,
                                              const __half* __restrict__ Ah,
                                              const __half* __restrict__ Bh) {
    int tid = threadIdx.x;
    #pragma unroll
    for (int i = 0; i < 4; i++) {                  // A: 128 rows x 128B
        int v = tid + i * 256;
        int r = v >> 3, kc = v & 7;
        const void* g = Ah + (size_t)(bm + r) * 256 + c * 64 + kc * 8;
        cp16(sdst + SWZ(r * 128 + kc * 16), g);
    }
    uint32_t bdst = sdst + 16384;
    #pragma unroll
    for (int i = 0; i < 4; i++) {                  // B: 128 n-rows x 128B
        int v = tid + i * 256;
        int r = v >> 3, kc = v & 7;
        const void* g = Bh + (size_t)(nb * 128 + r) * 256 + c * 64 + kc * 8;
        cp16(bdst + SWZ(r * 128 + kc * 16), g);
    }
}

__global__ __launch_bounds__(256)
void gemm_tc_kernel(const __half* __restrict__ Ah, const __half* __restrict__ Bh,
                    const float* __restrict__ bias, __half* __restrict__ Yh, __half* __restrict__ Zh) {
    extern __shared__ char smem[];
    uint32_t sb = smem_u32(smem);
    int tid = threadIdx.x, wid = tid >> 5, lane = tid & 31;
    int bm = blockIdx.x * 128;
    int nb = blockIdx.y;
    int wm = wid >> 1, wn = wid & 1;

    float acc[2][8][4];
    #pragma unroll
    for (int t = 0; t < 2; t++)
        #pragma unroll
        for (int u = 0; u < 8; u++)
            #pragma unroll
            for (int e = 0; e < 4; e++) acc[t][u][e] = 0.f;

    load_chunk_cp(sb, 0, bm, nb, Ah, Bh);
    cp_commit();

    for (int ch = 0; ch < K_CHUNKS; ch++) {
        int st = ch & 1;
        if (ch + 1 < K_CHUNKS) {
            load_chunk_cp(sb + (st ^ 1) * 32768, ch + 1, bm, nb, Ah, Bh);
            cp_commit();
            cp_wait1();
        } else {
            cp_wait0();
        }
        __syncthreads();

        uint32_t As = sb + st * 32768;
        uint32_t Bs = As + 16384;
        #pragma unroll
        for (int s = 0; s < 4; s++) {
            uint32_t a[2][4], bfrag[4][4];
            #pragma unroll
            for (int t = 0; t < 2; t++) {
                int m_local = wm * 32 + t * 16 + ((lane >> 3) & 1) * 8 + (lane & 7);
                int kseg = s * 2 + (lane >> 4);
                ldmx4(a[t], As + SWZ(m_local * 128 + kseg * 16));
            }
            #pragma unroll
            for (int j = 0; j < 4; j++) {
                int n_local = wn * 64 + (2 * j + (lane >> 4)) * 8 + (lane & 7);
                int kseg = s * 2 + ((lane >> 3) & 1);
                ldmx4(bfrag[j], Bs + SWZ(n_local * 128 + kseg * 16));
            }
            #pragma unroll
            for (int t = 0; t < 2; t++)
                #pragma unroll
                for (int u = 0; u < 8; u++)
                    mma16816(acc[t][u], a[t], bfrag[u >> 1][(u & 1) * 2],
                             bfrag[u >> 1][(u & 1) * 2 + 1]);
        }
        __syncthreads();
    }

    // epilogue (fp16 outputs)
    bool isY = (nb < 2);
    __half* C = isY ? Yh : Zh;
    int colbase = (nb & 1) * 128 + wn * 64;
    #pragma unroll
    for (int t = 0; t < 2; t++) {
        int m0 = bm + wm * 32 + t * 16 + (lane >> 2);
        #pragma unroll
        for (int u = 0; u < 8; u++) {
            int col = colbase + u * 8 + (lane & 3) * 2;
            float v0 = acc[t][u][0], v1 = acc[t][u][1];
            float v2 = acc[t][u][2], v3 = acc[t][u][3];
            if (!isY) {
                float2 bb = *(const float2*)(bias + col);
                v0 += bb.x; v1 += bb.y; v2 += bb.x; v3 += bb.y;
            }
            if (m0 < NN)     *(__half2*)(C + (size_t)m0 * 256 + col)       = __floats2half2_rn(v0, v1);
            if (m0 + 8 < NN) *(__half2*)(C + (size_t)(m0 + 8) * 256 + col) = __floats2half2_rn(v2, v3);
        }
    }
}

// ------ aggregation: out = relu(gather_sum(Yh) + Zh) -------------------------
// Ahout != nullptr: write fp16 (layers 0..4). F32out != nullptr: write fp32 (last layer).
__global__ void aggregate_relu_kernel(const __half* __restrict__ Yh, const __half* __restrict__ Zh,
                                      const int* __restrict__ rowptr, const int* __restrict__ csr,
                                      __half* __restrict__ Ahout, float* __restrict__ F32out,
                                      int n) {
    int warp = (blockIdx.x * blockDim.x + threadIdx.x) >> 5;
    int lane = threadIdx.x & 31;
    if (warp >= n) return;
    int beg = rowptr[warp], end = rowptr[warp + 1];
    size_t off = (size_t)warp * HH + lane * 8;

    float4 acc0, acc1;
    {
        uint4 q = *(const uint4*)(Zh + off);
        float2 f0 = __half22float2(*(__half2*)&q.x);
        float2 f1 = __half22float2(*(__half2*)&q.y);
        float2 f2 = __half22float2(*(__half2*)&q.z);
        float2 f3 = __half22float2(*(__half2*)&q.w);
        acc0 = make_float4(f0.x, f0.y, f1.x, f1.y);
        acc1 = make_float4(f2.x, f2.y, f3.x, f3.y);
    }
    for (int e = beg; e < end; e++) {
        int s0 = csr[e];
        uint4 q = *(const uint4*)(Yh + (size_t)s0 * HH + lane * 8);   // 8 halves
        float2 f0 = __half22float2(*(__half2*)&q.x);
        float2 f1 = __half22float2(*(__half2*)&q.y);
        float2 f2 = __half22float2(*(__half2*)&q.z);
        float2 f3 = __half22float2(*(__half2*)&q.w);
        acc0.x += f0.x; acc0.y += f0.y; acc0.z += f1.x; acc0.w += f1.y;
        acc1.x += f2.x; acc1.y += f2.y; acc1.z += f3.x; acc1.w += f3.y;
    }
    acc0.x = fmaxf(acc0.x, 0.f); acc0.y = fmaxf(acc0.y, 0.f);
    acc0.z = fmaxf(acc0.z, 0.f); acc0.w = fmaxf(acc0.w, 0.f);
    acc1.x = fmaxf(acc1.x, 0.f); acc1.y = fmaxf(acc1.y, 0.f);
    acc1.z = fmaxf(acc1.z, 0.f); acc1.w = fmaxf(acc1.w, 0.f);

    if (F32out) {
        *(float4*)(F32out + off)     = acc0;
        *(float4*)(F32out + off + 4) = acc1;
    }
    if (Ahout) {
        uint4 o;
        *(__half2*)&o.x = __floats2half2_rn(acc0.x, acc0.y);
        *(__half2*)&o.y = __floats2half2_rn(acc0.z, acc0.w);
        *(__half2*)&o.z = __floats2half2_rn(acc1.x, acc1.y);
        *(__half2*)&o.w = __floats2half2_rn(acc1.z, acc1.w);
        *(uint4*)(Ahout + (size_t)warp * 256 + lane * 8) = o;
    }
}

// ---------------- mean pool over sorted batch ids ----------------------------
__device__ __forceinline__ int lower_bound_dev(const int* a, int n, int key) {
    int lo = 0, hi = n;
    while (lo < hi) {
        int mid = (lo + hi) >> 1;
        if (a[mid] < key) lo = mid + 1; else hi = mid;
    }
    return lo;
}

__global__ void pool_kernel(const float* __restrict__ H, const int* __restrict__ batch,
                            float* __restrict__ pooled, int n) {
    int g = blockIdx.x;
    int j = threadIdx.x;  // 256
    __shared__ int s_lo, s_hi;
    if (j == 0) {
        s_lo = lower_bound_dev(batch, n, g);
        s_hi = lower_bound_dev(batch, n, g + 1);
    }
    __syncthreads();
    int lo = s_lo, hi = s_hi;
    float acc = 0.f;
    for (int nd = lo; nd < hi; nd++) acc += H[(size_t)nd * HH + j];
    int cnt = hi - lo;
    pooled[g * HH + j] = acc / (float)max(cnt, 1);
}

// ---------------- output head ------------------------------------------------
__global__ void head_kernel(const float* __restrict__ pooled, const float* __restrict__ w_out,
                            const float* __restrict__ b_out, float* __restrict__ out) {
    int g = blockIdx.x;
    int j = threadIdx.x;  // 32, guard 24
    if (j >= OUTD) return;
    float acc = b_out[j];
    #pragma unroll 8
    for (int k = 0; k < HH; k++)
        acc += pooled[g * HH + k] * w_out[k * OUTD + j];
    out[g * OUTD + j] = acc;
}

// ---------------- launch -----------------------------------------------------
extern "C" void kernel_launch(void* const* d_in, const int* in_sizes, int n_in,
                              void* d_out, int out_size) {
    const float* x       = (const float*)d_in[0];
    const int*   ei      = (const int*)d_in[1];
    const int*   batch   = (const int*)d_in[2];
    const float* w_rel1  = (const float*)d_in[3];
    const float* w_root1 = (const float*)d_in[4];
    const float* b1      = (const float*)d_in[5];
    const float* w_rel   = (const float*)d_in[6];   // 6 x 256 x 256
    const float* w_root  = (const float*)d_in[7];
    const float* b       = (const float*)d_in[8];   // 6 x 256
    const float* w_out   = (const float*)d_in[9];
    const float* b_out   = (const float*)d_in[10];
    float* out = (float*)d_out;

    const int* src = ei;        // edge_index[0]
    const int* dst = ei + EE;   // edge_index[1]

    float *hf, *agg3, *pooled;
    __half *yh, *zh, *Ah, *Bh;
    int *deg, *rowptr, *cursor, *csr, *bsums;
    cudaGetSymbolAddress((void**)&hf, g_hf);
    cudaGetSymbolAddress((void**)&yh, g_yh);
    cudaGetSymbolAddress((void**)&zh, g_zh);
    cudaGetSymbolAddress((void**)&agg3, g_agg3);
    cudaGetSymbolAddress((void**)&pooled, g_pooled);
    cudaGetSymbolAddress((void**)&deg, g_deg);
    cudaGetSymbolAddress((void**)&rowptr, g_rowptr);
    cudaGetSymbolAddress((void**)&cursor, g_cursor);
    cudaGetSymbolAddress((void**)&csr, g_csr);
    cudaGetSymbolAddress((void**)&bsums, g_bsums);
    cudaGetSymbolAddress((void**)&Ah, g_Ah);
    cudaGetSymbolAddress((void**)&Bh, g_Bh);

    cudaFuncSetAttribute(gemm_tc_kernel, cudaFuncAttributeMaxDynamicSharedMemorySize, GEMM_SMEM_TOTAL);

    // ---- build CSR (once per launch) ----
    zero_int_kernel<<<(NN + 255) / 256, 256>>>(deg, NN);
    zero_int_kernel<<<(NN + 255) / 256, 256>>>(cursor, NN);
    count_deg_kernel<<<(EE + 255) / 256, 256>>>(dst, deg, EE);
    scan_pass1<<<SCAN_BLOCKS, 256>>>(deg, bsums, NN);
    scan_pass2<<<1, 256>>>(bsums, SCAN_BLOCKS);
    scan_pass3<<<SCAN_BLOCKS, 256>>>(deg, bsums, rowptr, NN);
    fill_csr_kernel<<<(EE + 255) / 256, 256>>>(src, dst, rowptr, cursor, csr, EE);

    // ---- weight prep (fp16, K-major) ----
    prep_weights_kernel<<<(6 * 512 * 256 + 255) / 256, 256>>>(w_rel, w_root, Bh);

    // ---- layer 1 (3 -> 256), fp32 -> Ah fp16 directly ----
    aggx_kernel<<<(NN + 255) / 256, 256>>>(x, rowptr, csr, agg3, NN);
    layer1_kernel<<<NN, 256>>>(x, agg3, w_rel1, w_root1, b1, Ah);

    // ---- layers 2..7 (256 -> 256), tensor cores via mma.sync fp16 ----
    dim3 ggrid(NPAD / 128, 4);
    for (int i = 0; i < 6; i++) {
        gemm_tc_kernel<<<ggrid, 256, GEMM_SMEM_TOTAL>>>(Ah, Bh + (size_t)i * 512 * 256,
                                                        b + i * HH, yh, zh);
        bool last = (i == 5);
        aggregate_relu_kernel<<<(NN * 32 + 255) / 256, 256>>>(
            yh, zh, rowptr, csr,
            last ? (__half*)nullptr : Ah,
            last ? hf : (float*)nullptr, NN);
    }

    // ---- pool + head ----
    pool_kernel<<<GG, 256>>>(hf, batch, pooled, NN);
    head_kernel<<<GG, 32>>>(pooled, w_out, b_out, out);
}